// round 12
// baseline (speedup 1.0000x reference)
#include <cuda_runtime.h>
#include <cuda_fp16.h>
#include <math.h>

#define BATCH 4096
#define FEAT  40960
#define HID   1024
#define HID2  2048
#define NL1   64
#define NL2   32
#define GRP   32
#define NGRP  (BATCH / GRP)     // 128
#define NQ    4                 // k-quarters
#define QK    (HID2 / NQ)       // 512

// ---------------- static device scratch (no allocs allowed) ----------------
__device__ __half g_ftT[(size_t)FEAT * HID];             // 83.9 MB
__device__ __half g_h1[(size_t)BATCH * HID2];            // 16.8 MB
__device__ float  g_part[(size_t)NQ * NGRP * GRP * NL1]; // 4.2 MB l1 partials
__device__ int    g_done;
__device__ int    g_cnt[NGRP];                           // per-group quarter counters

// =========================================================================
// Reset kernel: zero transpose flag + group counters
// =========================================================================
__global__ void reset_kernel()
{
    if (threadIdx.x < NGRP) g_cnt[threadIdx.x] = 0;
    if (threadIdx.x == 0)   g_done = 0;
}

// =========================================================================
// Mega-kernel (round-4 exact):
//   CTAs [0, NT)        : transpose ft_w -> g_ftT (fp16), signal.
//   CTAs [NT, NT+BATCH) : scan -> wait -> gather -> h1 (fp16).
// =========================================================================
#define T1      256
#define NT      512
#define MAXIDX  256
#define NTILE_F (FEAT / 32)                 // 1280
#define NTILES  (NTILE_F * (HID / 64))      // 20480

__global__ __launch_bounds__(T1) void mega_kernel(
    const float* __restrict__ wf,    // [B, FEAT]
    const float* __restrict__ bfeat, // [B, FEAT]
    const float* __restrict__ stm,   // [B, 1]
    const float* __restrict__ ftw,   // [HID, FEAT]
    const float* __restrict__ ft_b)  // [HID]
{
    __shared__ union {
        float tile[64][33];
        struct { int idxW[MAXIDX]; int idxB[MAXIDX]; int cw; int cb; } s;
    } sm;

    const int tid = threadIdx.x;

    if (blockIdx.x < NT) {
        // ---------------- transpose: 40 tiles of 64h x 32f per CTA ----------------
        for (int t = blockIdx.x; t < NTILES; t += NT) {
            const int f0 = (t % NTILE_F) * 32;
            const int h0 = (t / NTILE_F) * 64;
#pragma unroll
            for (int u = 0; u < 8; u++) {
                int idx = tid + u * T1;
                int hl = idx >> 5, fl = idx & 31;
                sm.tile[hl][fl] = __ldcs(ftw + (size_t)(h0 + hl) * FEAT + f0 + fl);
            }
            __syncthreads();
#pragma unroll
            for (int u = 0; u < 4; u++) {
                int idx = tid + u * T1;
                int fl = idx >> 5, hp = idx & 31;
                __half2 v = __floats2half2_rn(sm.tile[2 * hp][fl], sm.tile[2 * hp + 1][fl]);
                *reinterpret_cast<__half2*>(g_ftT + (size_t)(f0 + fl) * HID + h0 + 2 * hp) = v;
            }
            __syncthreads();
        }
        __threadfence();
        __syncthreads();
        if (tid == 0) atomicAdd(&g_done, 1);
        return;
    }

    // ---------------- scan ----------------
    const int b = blockIdx.x - NT;

    if (tid == 0) { sm.s.cw = 0; sm.s.cb = 0; }
    __syncthreads();
    {
        const float4* pw = (const float4*)(wf    + (size_t)b * FEAT);
        const float4* pb = (const float4*)(bfeat + (size_t)b * FEAT);
        for (int base = 0; base < FEAT / 4; base += 4 * T1) {
            float4 v[4], w[4];
#pragma unroll
            for (int u = 0; u < 4; u++) {
                v[u] = __ldcs(pw + base + tid + u * T1);
                w[u] = __ldcs(pb + base + tid + u * T1);
            }
#pragma unroll
            for (int u = 0; u < 4; u++) {
                int i = base + tid + u * T1;
                if (v[u].x != 0.f) { int q = atomicAdd(&sm.s.cw, 1); if (q < MAXIDX) sm.s.idxW[q] = 4*i;   }
                if (v[u].y != 0.f) { int q = atomicAdd(&sm.s.cw, 1); if (q < MAXIDX) sm.s.idxW[q] = 4*i+1; }
                if (v[u].z != 0.f) { int q = atomicAdd(&sm.s.cw, 1); if (q < MAXIDX) sm.s.idxW[q] = 4*i+2; }
                if (v[u].w != 0.f) { int q = atomicAdd(&sm.s.cw, 1); if (q < MAXIDX) sm.s.idxW[q] = 4*i+3; }
                if (w[u].x != 0.f) { int q = atomicAdd(&sm.s.cb, 1); if (q < MAXIDX) sm.s.idxB[q] = 4*i;   }
                if (w[u].y != 0.f) { int q = atomicAdd(&sm.s.cb, 1); if (q < MAXIDX) sm.s.idxB[q] = 4*i+1; }
                if (w[u].z != 0.f) { int q = atomicAdd(&sm.s.cb, 1); if (q < MAXIDX) sm.s.idxB[q] = 4*i+2; }
                if (w[u].w != 0.f) { int q = atomicAdd(&sm.s.cb, 1); if (q < MAXIDX) sm.s.idxB[q] = 4*i+3; }
            }
        }
    }
    __syncthreads();

    // wait for transpose completion
    if (tid == 0) {
        while (atomicAdd(&g_done, 0) < NT) __nanosleep(128);
    }
    __syncthreads();
    __threadfence();

    // ---------------- gather ----------------
    const float4 bias = *reinterpret_cast<const float4*>(ft_b + 4 * tid);
    float4 accW = bias, accB = bias;
    const int nW = min(sm.s.cw, MAXIDX);
#pragma unroll 4
    for (int j = 0; j < nW; j++) {
        const uint2 raw = *reinterpret_cast<const uint2*>(
            g_ftT + (size_t)sm.s.idxW[j] * HID + 4 * tid);
        const float2 lo = __half22float2(*reinterpret_cast<const __half2*>(&raw.x));
        const float2 hi = __half22float2(*reinterpret_cast<const __half2*>(&raw.y));
        accW.x += lo.x; accW.y += lo.y; accW.z += hi.x; accW.w += hi.y;
    }
    const int nB = min(sm.s.cb, MAXIDX);
#pragma unroll 4
    for (int j = 0; j < nB; j++) {
        const uint2 raw = *reinterpret_cast<const uint2*>(
            g_ftT + (size_t)sm.s.idxB[j] * HID + 4 * tid);
        const float2 lo = __half22float2(*reinterpret_cast<const __half2*>(&raw.x));
        const float2 hi = __half22float2(*reinterpret_cast<const __half2*>(&raw.y));
        accB.x += lo.x; accB.y += lo.y; accB.z += hi.x; accB.w += hi.y;
    }

    // stm select + clip + store h1 (fp16)
    const float s = __ldg(stm + b);
    float cw[4] = {fminf(fmaxf(accW.x,0.f),1.f), fminf(fmaxf(accW.y,0.f),1.f),
                   fminf(fmaxf(accW.z,0.f),1.f), fminf(fmaxf(accW.w,0.f),1.f)};
    float cb[4] = {fminf(fmaxf(accB.x,0.f),1.f), fminf(fmaxf(accB.y,0.f),1.f),
                   fminf(fmaxf(accB.z,0.f),1.f), fminf(fmaxf(accB.w,0.f),1.f)};
    __half* o = g_h1 + (size_t)b * HID2;
    uint2 pf, ps;
    *reinterpret_cast<__half2*>(&pf.x) = __floats2half2_rn(
        s*cw[0]+(1.f-s)*cb[0], s*cw[1]+(1.f-s)*cb[1]);
    *reinterpret_cast<__half2*>(&pf.y) = __floats2half2_rn(
        s*cw[2]+(1.f-s)*cb[2], s*cw[3]+(1.f-s)*cb[3]);
    *reinterpret_cast<__half2*>(&ps.x) = __floats2half2_rn(
        s*cb[0]+(1.f-s)*cw[0], s*cb[1]+(1.f-s)*cw[1]);
    *reinterpret_cast<__half2*>(&ps.y) = __floats2half2_rn(
        s*cb[2]+(1.f-s)*cw[2], s*cb[3]+(1.f-s)*cw[3]);
    *reinterpret_cast<uint2*>(o + 4 * tid)       = pf;
    *reinterpret_cast<uint2*>(o + HID + 4 * tid) = ps;
}

// =========================================================================
// Fused MLP: grid = NGRP*NQ = 512 CTAs, 256 threads.
// CTA (grp, q): partial l1 GEMM over k in [512q, 512q+512) for rows
// [32*grp, +32), store partials; LAST quarter of each group (atomic
// handoff, no spinning) reduces + bias + clip + l2 + l3 + sigmoid + out.
// =========================================================================
#define T2    256
#define TB    32
#define CHUNK 64
#define NCHQ  (QK / CHUNK)   // 8
#define HPAD  36
#define WPAD  66

__global__ __launch_bounds__(T2) void mlp_kernel(
    const float* __restrict__ l1_w, const float* __restrict__ l1_b,
    const float* __restrict__ l2_w, const float* __restrict__ l2_b,
    const float* __restrict__ l3_w, const float* __restrict__ l3_b,
    float* __restrict__ out, int out_size)
{
    __shared__ union {
        struct {
            __align__(16) float hst[2][CHUNK][HPAD];   // 18.4 KB
            __align__(16) float wst[2][CHUNK][WPAD];   // 33.8 KB
        } g;
        struct {
            float h2s[GRP][NL1 + 1];
            float h3s[GRP][NL2 + 1];
            float l2s[NL2][NL1 + 1];
        } e;
    } sm;
    __shared__ int sm_last;

    const int tid  = threadIdx.x;
    const int grp  = blockIdx.x >> 2;
    const int q    = blockIdx.x & 3;
    const int row0 = grp * TB;
    const int kb   = q * QK;
    const int tx   = tid & 31;   // out pair {2tx, 2tx+1}
    const int ty   = tid >> 5;   // row quad {4ty..4ty+3}

    __half2 hreg[4];
    float   wreg[16];
    {
#pragma unroll
        for (int u = 0; u < 4; u++) {
            int idx = tid + u * T2; int r = idx >> 5, kp = idx & 31;
            hreg[u] = *reinterpret_cast<const __half2*>(
                g_h1 + (size_t)(row0 + r) * HID2 + kb + 2 * kp);
        }
#pragma unroll
        for (int u = 0; u < 16; u++) {
            int idx = tid + u * T2; int oo = idx >> 6, kk = idx & 63;
            wreg[u] = __ldg(l1_w + (size_t)oo * HID2 + kb + kk);
        }
#pragma unroll
        for (int u = 0; u < 4; u++) {
            int idx = tid + u * T2; int r = idx >> 5, kp = idx & 31;
            float2 f = __half22float2(hreg[u]);
            sm.g.hst[0][2 * kp][r]     = f.x;
            sm.g.hst[0][2 * kp + 1][r] = f.y;
        }
#pragma unroll
        for (int u = 0; u < 16; u++) {
            int idx = tid + u * T2; int oo = idx >> 6, kk = idx & 63;
            sm.g.wst[0][kk][oo] = wreg[u];
        }
    }
    __syncthreads();

    float acc[4][2];
#pragma unroll
    for (int i = 0; i < 4; i++) { acc[i][0] = 0.f; acc[i][1] = 0.f; }

    for (int c = 0; c < NCHQ; c++) {
        const int buf = c & 1;
        if (c + 1 < NCHQ) {
            const int kc = kb + (c + 1) * CHUNK;
#pragma unroll
            for (int u = 0; u < 4; u++) {
                int idx = tid + u * T2; int r = idx >> 5, kp = idx & 31;
                hreg[u] = *reinterpret_cast<const __half2*>(
                    g_h1 + (size_t)(row0 + r) * HID2 + kc + 2 * kp);
            }
#pragma unroll
            for (int u = 0; u < 16; u++) {
                int idx = tid + u * T2; int oo = idx >> 6, kk = idx & 63;
                wreg[u] = __ldg(l1_w + (size_t)oo * HID2 + kc + kk);
            }
        }
#pragma unroll 16
        for (int k = 0; k < CHUNK; k++) {
            const float4 h = *reinterpret_cast<const float4*>(&sm.g.hst[buf][k][4 * ty]);
            const float2 w = *reinterpret_cast<const float2*>(&sm.g.wst[buf][k][2 * tx]);
            acc[0][0] = fmaf(h.x, w.x, acc[0][0]); acc[0][1] = fmaf(h.x, w.y, acc[0][1]);
            acc[1][0] = fmaf(h.y, w.x, acc[1][0]); acc[1][1] = fmaf(h.y, w.y, acc[1][1]);
            acc[2][0] = fmaf(h.z, w.x, acc[2][0]); acc[2][1] = fmaf(h.z, w.y, acc[2][1]);
            acc[3][0] = fmaf(h.w, w.x, acc[3][0]); acc[3][1] = fmaf(h.w, w.y, acc[3][1]);
        }
        if (c + 1 < NCHQ) {
            const int nb = (c + 1) & 1;
#pragma unroll
            for (int u = 0; u < 4; u++) {
                int idx = tid + u * T2; int r = idx >> 5, kp = idx & 31;
                float2 f = __half22float2(hreg[u]);
                sm.g.hst[nb][2 * kp][r]     = f.x;
                sm.g.hst[nb][2 * kp + 1][r] = f.y;
            }
#pragma unroll
            for (int u = 0; u < 16; u++) {
                int idx = tid + u * T2; int oo = idx >> 6, kk = idx & 63;
                sm.g.wst[nb][kk][oo] = wreg[u];
            }
        }
        __syncthreads();
    }

    // store partials: g_part[q][grp][row][out]
    {
        float* dst = g_part + (((size_t)q * NGRP + grp) * TB) * NL1;
#pragma unroll
        for (int i = 0; i < 4; i++) {
            float2 v = make_float2(acc[i][0], acc[i][1]);
            *reinterpret_cast<float2*>(dst + (4 * ty + i) * NL1 + 2 * tx) = v;
        }
    }

    // ---- atomic handoff: last quarter of this group runs the epilogue ----
    __threadfence();
    __syncthreads();
    if (tid == 0) sm_last = (atomicAdd(&g_cnt[grp], 1) == NQ - 1);
    __syncthreads();
    if (!sm_last) return;
    __threadfence();   // acquire other quarters' partials

    // ---- epilogue: reduce + bias + clip -> l2 -> l3 -> sigmoid ----
    for (int i = tid; i < NL2 * NL1; i += T2) sm.e.l2s[i >> 6][i & 63] = l2_w[i];

    const float* base = g_part + (size_t)grp * TB * NL1;
    for (int p = tid; p < GRP * NL1; p += T2) {
        int r = p >> 6, o = p & 63;
        float s = __ldg(l1_b + o);
#pragma unroll
        for (int qq = 0; qq < NQ; qq++)
            s += base[(size_t)qq * NGRP * TB * NL1 + r * NL1 + o];
        sm.e.h2s[r][o] = fminf(fmaxf(s, 0.f), 1.f);
    }
    __syncthreads();

    for (int p = tid; p < GRP * NL2; p += T2) {
        int r = p >> 5, oo = p & 31;
        float s = __ldg(l2_b + oo);
#pragma unroll
        for (int k = 0; k < NL1; k++) s = fmaf(sm.e.h2s[r][k], sm.e.l2s[oo][k], s);
        sm.e.h3s[r][oo] = fminf(fmaxf(s, 0.f), 1.f);
    }
    __syncthreads();

    if (tid < GRP) {
        float s = __ldg(l3_b);
#pragma unroll
        for (int k = 0; k < NL2; k++) s = fmaf(sm.e.h3s[tid][k], __ldg(l3_w + k), s);
        float sig = 1.f / (1.f + expf(-s));
        int r = row0 + tid;
        if (out_size >= 2 * BATCH) {
            out[r]         = sig;
            out[BATCH + r] = s;
        } else {
            out[r] = sig;
        }
    }
}

// =========================================================================
extern "C" void kernel_launch(void* const* d_in, const int* in_sizes, int n_in,
                              void* d_out, int out_size)
{
    const float* wf    = (const float*)d_in[0];
    const float* bfeat = (const float*)d_in[1];
    const float* stm   = (const float*)d_in[2];
    const float* ft_w  = (const float*)d_in[3];
    const float* ft_b  = (const float*)d_in[4];
    const float* l1_w  = (const float*)d_in[5];
    const float* l1_b  = (const float*)d_in[6];
    const float* l2_w  = (const float*)d_in[7];
    const float* l2_b  = (const float*)d_in[8];
    const float* l3_w  = (const float*)d_in[9];
    const float* l3_b  = (const float*)d_in[10];
    float* out = (float*)d_out;

    reset_kernel<<<1, 128>>>();
    mega_kernel<<<NT + BATCH, T1>>>(wf, bfeat, stm, ft_w, ft_b);
    mlp_kernel<<<NGRP * NQ, T2>>>(l1_w, l1_b, l2_w, l2_b, l3_w, l3_b, out, out_size);
}